// round 5
// baseline (speedup 1.0000x reference)
#include <cuda_runtime.h>
#include <cstdint>
#include <math.h>

#define B_  2
#define T_  2048
#define E_  1024
#define H_  16
#define D_  64
#define BH_ (B_*H_)       // 32

// ---------------------------------------------------------------------------
// Device scratch
// ---------------------------------------------------------------------------
__device__ float g_q[(size_t)BH_ * T_ * D_];
__device__ float g_k[(size_t)BH_ * T_ * D_];
__device__ float g_v[(size_t)BH_ * T_ * D_];
__device__ float g_m[(size_t)BH_ * T_];       // column max (log2 domain)
__device__ float g_zinv[(size_t)BH_ * T_];    // column 1/sum

// scale * log2(e): softmax computed in base-2 domain
#define KS2 0.18033688011112042592f

// ---------------------------------------------------------------------------
// helpers
// ---------------------------------------------------------------------------
__device__ __forceinline__ uint32_t f2tf(float f) {
    uint32_t u;
    asm("cvt.rna.tf32.f32 %0, %1;" : "=r"(u) : "f"(f));
    return u;
}

__device__ __forceinline__ void mma8(float* c, const uint32_t* a, const uint32_t* b) {
    asm volatile(
        "mma.sync.aligned.m16n8k8.row.col.f32.tf32.tf32.f32 "
        "{%0,%1,%2,%3},{%4,%5,%6,%7},{%8,%9},{%0,%1,%2,%3};"
        : "+f"(c[0]), "+f"(c[1]), "+f"(c[2]), "+f"(c[3])
        : "r"(a[0]), "r"(a[1]), "r"(a[2]), "r"(a[3]), "r"(b[0]), "r"(b[1]));
}

// A-operand fragment (16 rows x k8) via one ldmatrix.x4. base row-major, S words/row.
__device__ __forceinline__ void ldsmA(uint32_t* r, const uint32_t* base,
                                      int row0, int ko, int lane, int S) {
    const uint32_t* p = base +
        (size_t)(row0 + (lane & 7) + ((lane >> 3) & 1) * 8) * S + ko + (lane >> 4) * 4;
    uint32_t addr = (uint32_t)__cvta_generic_to_shared(p);
    asm volatile("ldmatrix.sync.aligned.m8n8.x4.shared.b16 {%0,%1,%2,%3}, [%4];"
                 : "=r"(r[0]), "=r"(r[1]), "=r"(r[2]), "=r"(r[3]) : "r"(addr));
}

// Two B-operand fragments (cols n0..n0+15 x k8) via one ldmatrix.x4.
// r[0],r[1] = frag at n0; r[2],r[3] = frag at n0+8.
__device__ __forceinline__ void ldsmB2(uint32_t* r, const uint32_t* base,
                                       int n0, int ko, int lane, int S) {
    const uint32_t* p = base +
        (size_t)(n0 + ((lane >> 4) << 3) + (lane & 7)) * S + ko + ((lane >> 3) & 1) * 4;
    uint32_t addr = (uint32_t)__cvta_generic_to_shared(p);
    asm volatile("ldmatrix.sync.aligned.m8n8.x4.shared.b16 {%0,%1,%2,%3}, [%4];"
                 : "=r"(r[0]), "=r"(r[1]), "=r"(r[2]), "=r"(r[3]) : "r"(addr));
}

// fast 2^y for y <= 0, FMA-pipe only. rel err ~2.4e-6.
__device__ __forceinline__ float fexp2(float y) {
    y = fmaxf(y, -120.f);
    float t = y + 12582912.f;              // round-to-nearest-int via magic const
    int   iy = __float_as_int(t);          // low mantissa bits hold n
    float fl = t - 12582912.f;             // float(n)
    float f  = y - fl;                     // f in [-0.5, 0.5]
    float p = 0.0013333558f;
    p = fmaf(p, f, 0.0096181291f);
    p = fmaf(p, f, 0.0555041087f);
    p = fmaf(p, f, 0.2402265069f);
    p = fmaf(p, f, 0.6931471806f);
    p = fmaf(p, f, 1.0f);
    return __int_as_float(__float_as_int(p) + (iy << 23));   // p * 2^n
}

// ---------------------------------------------------------------------------
// Kernel 1: fused QKV projection, 2 heads per block.
// Block tile 128(M) x 128(N = 2 heads x 64), 4 warps of 64x64, K-tile 32.
// ---------------------------------------------------------------------------
__global__ __launch_bounds__(128) void proj_kernel(const float* __restrict__ X,
                                                   const float* __restrict__ qw,
                                                   const float* __restrict__ kw,
                                                   const float* __restrict__ vw,
                                                   const float* __restrict__ qb,
                                                   const float* __restrict__ kb,
                                                   const float* __restrict__ vb,
                                                   float* __restrict__ oq,
                                                   float* __restrict__ ok,
                                                   float* __restrict__ ov)
{
    const float* W; const float* bias; float* out;
    if (blockIdx.z == 0)      { W = qw; bias = qb; out = oq; }
    else if (blockIdx.z == 1) { W = kw; bias = kb; out = ok; }
    else                      { W = vw; bias = vb; out = ov; }

    __shared__ __align__(16) uint32_t As[128][36];   // [m][k]
    __shared__ __align__(16) uint32_t Bs[128][36];   // [n][k] (n = 2 heads x 64 d)

    const int m0   = blockIdx.x * 128;
    const int h0   = blockIdx.y * 2;
    const int tid  = threadIdx.x;
    const int lane = tid & 31;
    const int warp = tid >> 5;
    const int wm   = warp >> 1;
    const int wn   = warp & 1;
    const int g    = lane >> 2;
    const int tg   = lane & 3;

    float acc[4][8][4] = {};

    for (int k0 = 0; k0 < E_; k0 += 32) {
        // A fill: 128 rows x 32 k (STS.128 after cvt)
        #pragma unroll
        for (int j = 0; j < 8; j++) {
            int q = tid + j * 128;
            int row = q >> 3, c = (q & 7) * 4;
            float4 v = *reinterpret_cast<const float4*>(
                X + (size_t)(m0 + row) * E_ + k0 + c);
            uint4 u;
            u.x = f2tf(v.x); u.y = f2tf(v.y); u.z = f2tf(v.z); u.w = f2tf(v.w);
            *reinterpret_cast<uint4*>(&As[row][c]) = u;
        }
        // B fill: W[h][e][d] -> Bs[n=hloc*64+d][e], lane = e
        #pragma unroll
        for (int j = 0; j < 8; j++) {
            int dq = warp + 4 * j;         // d-quad 0..31
            int n  = dq * 4;
            int h  = h0 + (n >> 6);
            int d  = n & 63;
            float4 v = *reinterpret_cast<const float4*>(
                W + ((size_t)h * E_ + k0 + lane) * D_ + d);
            Bs[n + 0][lane] = f2tf(v.x);
            Bs[n + 1][lane] = f2tf(v.y);
            Bs[n + 2][lane] = f2tf(v.z);
            Bs[n + 3][lane] = f2tf(v.w);
        }
        __syncthreads();

        #pragma unroll
        for (int ks = 0; ks < 4; ks++) {
            uint32_t a[4][4], b[16];
            #pragma unroll
            for (int mf = 0; mf < 4; mf++)
                ldsmA(a[mf], &As[0][0], wm * 64 + mf * 16, ks * 8, lane, 36);
            ldsmB2(&b[0],  &Bs[0][0], wn * 64 + 0,  ks * 8, lane, 36);
            ldsmB2(&b[4],  &Bs[0][0], wn * 64 + 16, ks * 8, lane, 36);
            ldsmB2(&b[8],  &Bs[0][0], wn * 64 + 32, ks * 8, lane, 36);
            ldsmB2(&b[12], &Bs[0][0], wn * 64 + 48, ks * 8, lane, 36);
            #pragma unroll
            for (int mf = 0; mf < 4; mf++)
                #pragma unroll
                for (int nf = 0; nf < 8; nf++)
                    mma8(acc[mf][nf], a[mf], &b[nf * 2]);
        }
        __syncthreads();
    }

    // epilogue: out (B,H,T,D) + bias
    #pragma unroll
    for (int mf = 0; mf < 4; mf++) {
        #pragma unroll
        for (int half = 0; half < 2; half++) {
            int m  = m0 + wm * 64 + mf * 16 + g + half * 8;
            int bb = m >> 11;
            int t  = m & (T_ - 1);
            #pragma unroll
            for (int nf = 0; nf < 8; nf++) {
                int nn = wn * 64 + nf * 8 + 2 * tg;
                int h  = h0 + (nn >> 6);
                int d  = nn & 63;
                float2 val;
                val.x = acc[mf][nf][half * 2 + 0] + bias[h * D_ + d];
                val.y = acc[mf][nf][half * 2 + 1] + bias[h * D_ + d + 1];
                *reinterpret_cast<float2*>(
                    out + (((size_t)bb * H_ + h) * T_ + t) * D_ + d) = val;
            }
        }
    }
}

// ---------------------------------------------------------------------------
// Pass A: column softmax stats (log2 domain), S never materialized.
// grid (s_tile=16, bh=32), block 256, 8 warps of 64t x 32s.
// ---------------------------------------------------------------------------
__global__ __launch_bounds__(256) void stats_kernel(const float* __restrict__ Q,
                                                    const float* __restrict__ K,
                                                    float* __restrict__ m_out,
                                                    float* __restrict__ z_out)
{
    extern __shared__ __align__(16) char smem_raw[];
    uint32_t* Ks = reinterpret_cast<uint32_t*>(smem_raw);                 // [128][68]
    uint32_t* Qs = Ks + 128 * 68;                                         // [128][68]
    float* redm = reinterpret_cast<float*>(Qs + 128 * 68);                // [2][128]
    float* redz = redm + 256;                                             // [2][128]
    float* mrun = redz + 256;                                             // [128]
    float* zrun = mrun + 128;                                             // [128]

    const int st   = blockIdx.x;
    const int bh   = blockIdx.y;
    const int tid  = threadIdx.x;
    const int lane = tid & 31;
    const int warp = tid >> 5;
    const int wm   = warp >> 2;
    const int wn   = warp & 3;
    const int g    = lane >> 2;
    const int tg   = lane & 3;

    const float* Kp = K + ((size_t)bh * T_ + st * 128) * D_;
    #pragma unroll
    for (int j = 0; j < 8; j++) {
        int q = tid + j * 256;
        int row = q >> 4, c = (q & 15) * 4;
        float4 v = *reinterpret_cast<const float4*>(Kp + (size_t)row * D_ + c);
        uint4 u;
        u.x = f2tf(v.x); u.y = f2tf(v.y); u.z = f2tf(v.z); u.w = f2tf(v.w);
        *reinterpret_cast<uint4*>(Ks + row * 68 + c) = u;
    }
    if (tid < 128) { mrun[tid] = -3.0e38f; zrun[tid] = 0.f; }
    __syncthreads();

    for (int it = st; it < T_ / 128; it++) {
        const float* Qp = Q + ((size_t)bh * T_ + it * 128) * D_;
        #pragma unroll
        for (int j = 0; j < 8; j++) {
            int q = tid + j * 256;
            int row = q >> 4, c = (q & 15) * 4;
            float4 v = *reinterpret_cast<const float4*>(Qp + (size_t)row * D_ + c);
            uint4 u;
            u.x = f2tf(v.x); u.y = f2tf(v.y); u.z = f2tf(v.z); u.w = f2tf(v.w);
            *reinterpret_cast<uint4*>(Qs + row * 68 + c) = u;
        }
        __syncthreads();

        float acc[4][4][4] = {};
        #pragma unroll
        for (int ks = 0; ks < 8; ks++) {
            uint32_t a[4][4], b[8];
            #pragma unroll
            for (int mf = 0; mf < 4; mf++)
                ldsmA(a[mf], Qs, wm * 64 + mf * 16, ks * 8, lane, 68);
            ldsmB2(&b[0], Ks, wn * 32 + 0,  ks * 8, lane, 68);
            ldsmB2(&b[4], Ks, wn * 32 + 16, ks * 8, lane, 68);
            #pragma unroll
            for (int mf = 0; mf < 4; mf++)
                #pragma unroll
                for (int nf = 0; nf < 4; nf++)
                    mma8(acc[mf][nf], a[mf], &b[nf * 2]);
        }

        // scale to log2 domain + causal mask (diag tile only)
        if (it == st) {
            #pragma unroll
            for (int mf = 0; mf < 4; mf++)
                #pragma unroll
                for (int hh = 0; hh < 2; hh++) {
                    int tl = wm * 64 + mf * 16 + g + hh * 8;
                    #pragma unroll
                    for (int nf = 0; nf < 4; nf++)
                        #pragma unroll
                        for (int ci = 0; ci < 2; ci++) {
                            int sl = wn * 32 + nf * 8 + 2 * tg + ci;
                            float x = acc[mf][nf][hh * 2 + ci] * KS2;
                            acc[mf][nf][hh * 2 + ci] = (tl >= sl) ? x : -3.0e38f;
                        }
                }
        } else {
            #pragma unroll
            for (int mf = 0; mf < 4; mf++)
                #pragma unroll
                for (int nf = 0; nf < 4; nf++)
                    #pragma unroll
                    for (int c = 0; c < 4; c++)
                        acc[mf][nf][c] *= KS2;
        }

        // per-warp column max
        #pragma unroll
        for (int nf = 0; nf < 4; nf++)
            #pragma unroll
            for (int ci = 0; ci < 2; ci++) {
                float v = -3.0e38f;
                #pragma unroll
                for (int mf = 0; mf < 4; mf++) {
                    v = fmaxf(v, acc[mf][nf][ci]);
                    v = fmaxf(v, acc[mf][nf][2 + ci]);
                }
                v = fmaxf(v, __shfl_xor_sync(0xffffffffu, v, 4));
                v = fmaxf(v, __shfl_xor_sync(0xffffffffu, v, 8));
                v = fmaxf(v, __shfl_xor_sync(0xffffffffu, v, 16));
                if (lane < 4) redm[wm * 128 + wn * 32 + nf * 8 + 2 * tg + ci] = v;
            }
        __syncthreads();

        // exp2-sum with combined tile max
        #pragma unroll
        for (int nf = 0; nf < 4; nf++)
            #pragma unroll
            for (int ci = 0; ci < 2; ci++) {
                int col = wn * 32 + nf * 8 + 2 * tg + ci;
                float mt = fmaxf(redm[col], redm[128 + col]);
                float zs = 0.f;
                #pragma unroll
                for (int mf = 0; mf < 4; mf++) {
                    zs += fexp2(acc[mf][nf][ci] - mt);
                    zs += fexp2(acc[mf][nf][2 + ci] - mt);
                }
                zs += __shfl_xor_sync(0xffffffffu, zs, 4);
                zs += __shfl_xor_sync(0xffffffffu, zs, 8);
                zs += __shfl_xor_sync(0xffffffffu, zs, 16);
                if (lane < 4) redz[wm * 128 + col] = zs;
            }
        __syncthreads();

        if (tid < 128) {
            float mt = fmaxf(redm[tid], redm[128 + tid]);
            float zt = redz[tid] + redz[128 + tid];
            float mo = mrun[tid];
            float mn = fmaxf(mo, mt);
            zrun[tid] = zrun[tid] * fexp2(mo - mn) + zt * fexp2(mt - mn);
            mrun[tid] = mn;
        }
        __syncthreads();
    }

    if (tid < 128) {
        int s = st * 128 + tid;
        m_out[bh * T_ + s] = mrun[tid];
        z_out[bh * T_ + s] = 1.0f / zrun[tid];
    }
}

// ---------------------------------------------------------------------------
// Pass B: out = P @ (V * zinv), P recomputed in log2 domain.
// grid (t_tile=16 reversed, bh=32), block 256.
// QK warp tile 64t x 16s; PV warp tile 32t x 32d.
// ---------------------------------------------------------------------------
__global__ __launch_bounds__(256) void out_kernel(const float* __restrict__ Q,
                                                  const float* __restrict__ K,
                                                  const float* __restrict__ V,
                                                  const float* __restrict__ mcol_g,
                                                  const float* __restrict__ zcol_g,
                                                  float* __restrict__ out)
{
    extern __shared__ __align__(16) char smem_raw[];
    uint32_t* Qs = reinterpret_cast<uint32_t*>(smem_raw);  // [128][68]
    uint32_t* Ps = Qs + 128 * 68;                          // [128][68]
    uint32_t* Ks = Ps + 128 * 68;                          // [64][68]
    uint32_t* Vs = Ks + 64 * 68;                           // [64][68]
    float* mcol  = reinterpret_cast<float*>(Vs + 64 * 68); // [64]
    float* zcol  = mcol + 64;                              // [64]

    const int tt   = (T_ / 128 - 1) - blockIdx.x;
    const int bh   = blockIdx.y;
    const int bb   = bh >> 4;
    const int h    = bh & 15;
    const int tid  = threadIdx.x;
    const int lane = tid & 31;
    const int warp = tid >> 5;
    const int g    = lane >> 2;
    const int tg   = lane & 3;

    const int wq_m = warp >> 2, wq_n = warp & 3;
    const int wp_m = warp & 3,  wp_n = warp >> 2;

    const int t0 = tt * 128;

    const float* Qp = Q + ((size_t)bh * T_ + t0) * D_;
    #pragma unroll
    for (int j = 0; j < 8; j++) {
        int q = tid + j * 256;
        int row = q >> 4, c = (q & 15) * 4;
        float4 v = *reinterpret_cast<const float4*>(Qp + (size_t)row * D_ + c);
        uint4 u;
        u.x = f2tf(v.x); u.y = f2tf(v.y); u.z = f2tf(v.z); u.w = f2tf(v.w);
        *reinterpret_cast<uint4*>(Qs + row * 68 + c) = u;
    }

    float oacc[2][4][4] = {};

    for (int s0 = 0; s0 <= t0 + 64; s0 += 64) {
        __syncthreads();

        const float* Kp = K + ((size_t)bh * T_ + s0) * D_;
        const float* Vp = V + ((size_t)bh * T_ + s0) * D_;
        #pragma unroll
        for (int j = 0; j < 4; j++) {
            int q = tid + j * 256;
            int row = q >> 4, c = (q & 15) * 4;
            float4 kv = *reinterpret_cast<const float4*>(Kp + (size_t)row * D_ + c);
            uint4 uk;
            uk.x = f2tf(kv.x); uk.y = f2tf(kv.y); uk.z = f2tf(kv.z); uk.w = f2tf(kv.w);
            *reinterpret_cast<uint4*>(Ks + row * 68 + c) = uk;
            float4 vv = *reinterpret_cast<const float4*>(Vp + (size_t)row * D_ + c);
            uint4 uv;
            uv.x = f2tf(vv.x); uv.y = f2tf(vv.y); uv.z = f2tf(vv.z); uv.w = f2tf(vv.w);
            *reinterpret_cast<uint4*>(Vs + row * 68 + c) = uv;
        }
        if (tid < 64) {
            mcol[tid] = mcol_g[bh * T_ + s0 + tid];
            zcol[tid] = zcol_g[bh * T_ + s0 + tid];
        }
        __syncthreads();

        // QK chunk: 128t x 64s
        float sacc[4][2][4] = {};
        #pragma unroll
        for (int ks = 0; ks < 8; ks++) {
            uint32_t a[4][4], b[4];
            #pragma unroll
            for (int mf = 0; mf < 4; mf++)
                ldsmA(a[mf], Qs, wq_m * 64 + mf * 16, ks * 8, lane, 68);
            ldsmB2(&b[0], Ks, wq_n * 16, ks * 8, lane, 68);
            #pragma unroll
            for (int mf = 0; mf < 4; mf++)
                #pragma unroll
                for (int nf = 0; nf < 2; nf++)
                    mma8(sacc[mf][nf], a[mf], &b[nf * 2]);
        }

        // exp2 + normalize + stage P (tf32)
        const bool needmask = (s0 + 63 > t0);
        #pragma unroll
        for (int mf = 0; mf < 4; mf++)
            #pragma unroll
            for (int hh = 0; hh < 2; hh++) {
                int tl = wq_m * 64 + mf * 16 + g + hh * 8;
                #pragma unroll
                for (int nf = 0; nf < 2; nf++)
                    #pragma unroll
                    for (int ci = 0; ci < 2; ci++) {
                        int sl = wq_n * 16 + nf * 8 + 2 * tg + ci;
                        float y = fmaf(sacc[mf][nf][hh * 2 + ci], KS2, -mcol[sl]);
                        float p = fexp2(y) * zcol[sl];
                        if (needmask && (s0 + sl > t0 + tl)) p = 0.f;
                        Ps[tl * 68 + sl] = f2tf(p);
                    }
            }
        __syncthreads();

        // PV: 128t x 64d over k=64
        #pragma unroll
        for (int ks = 0; ks < 8; ks++) {
            uint32_t a[2][4], b[4][2];
            #pragma unroll
            for (int mf = 0; mf < 2; mf++)
                ldsmA(a[mf], Ps, wp_m * 32 + mf * 16, ks * 8, lane, 68);
            #pragma unroll
            for (int nf = 0; nf < 4; nf++) {
                int cn = wp_n * 32 + nf * 8 + g;
                b[nf][0] = Vs[(ks * 8 + tg) * 68 + cn];
                b[nf][1] = Vs[(ks * 8 + tg + 4) * 68 + cn];
            }
            #pragma unroll
            for (int mf = 0; mf < 2; mf++)
                #pragma unroll
                for (int nf = 0; nf < 4; nf++)
                    mma8(oacc[mf][nf], a[mf], b[nf]);
        }
    }

    // epilogue: (B,T,H,D) head-major concat
    #pragma unroll
    for (int mf = 0; mf < 2; mf++)
        #pragma unroll
        for (int hh = 0; hh < 2; hh++) {
            int t = t0 + wp_m * 32 + mf * 16 + g + hh * 8;
            #pragma unroll
            for (int nf = 0; nf < 4; nf++) {
                int d = wp_n * 32 + nf * 8 + 2 * tg;
                float2 val;
                val.x = oacc[mf][nf][hh * 2 + 0];
                val.y = oacc[mf][nf][hh * 2 + 1];
                *reinterpret_cast<float2*>(
                    out + (((size_t)bb * T_ + t) * H_ + h) * D_ + d) = val;
            }
        }
}

// ---------------------------------------------------------------------------
// Launch
// ---------------------------------------------------------------------------
extern "C" void kernel_launch(void* const* d_in, const int* in_sizes, int n_in,
                              void* d_out, int out_size)
{
    const float* X   = (const float*)d_in[0];
    const float* k_w = (const float*)d_in[1];
    const float* k_b = (const float*)d_in[2];
    const float* q_w = (const float*)d_in[3];
    const float* q_b = (const float*)d_in[4];
    const float* v_w = (const float*)d_in[5];
    const float* v_b = (const float*)d_in[6];
    float* out = (float*)d_out;

    float *pq, *pk, *pv, *pm, *pz;
    cudaGetSymbolAddress((void**)&pq, g_q);
    cudaGetSymbolAddress((void**)&pk, g_k);
    cudaGetSymbolAddress((void**)&pv, g_v);
    cudaGetSymbolAddress((void**)&pm, g_m);
    cudaGetSymbolAddress((void**)&pz, g_zinv);

    const int SA = (2 * 128 * 68) * 4 + (256 + 256 + 128 + 128) * 4;        // 72704
    const int SB = (128 * 68 + 128 * 68 + 64 * 68 + 64 * 68) * 4 + 128 * 4; // 104960

    cudaFuncSetAttribute(stats_kernel, cudaFuncAttributeMaxDynamicSharedMemorySize, SA);
    cudaFuncSetAttribute(out_kernel,   cudaFuncAttributeMaxDynamicSharedMemorySize, SB);

    dim3 projGrid(B_ * T_ / 128, H_ / 2, 3);   // (32, 8, 3)
    proj_kernel<<<projGrid, 128>>>(X, q_w, k_w, v_w, q_b, k_b, v_b, pq, pk, pv);

    dim3 stGrid(T_ / 128, BH_);
    stats_kernel<<<stGrid, 256, SA>>>(pq, pk, pm, pz);

    dim3 outGrid(T_ / 128, BH_);
    out_kernel<<<outGrid, 256, SB>>>(pq, pk, pv, pm, pz, out);
}